// round 6
// baseline (speedup 1.0000x reference)
#include <cuda_runtime.h>
#include <cuda_bf16.h>
#include <cstdint>
#include <math.h>

// Problem constants
#define B_   2
#define S_   4096
#define E_   768
#define H_   12
#define DK_  64
#define BH_  (B_ * H_)          // 24
#define ROWS_ (B_ * S_)         // 8192

// ---------------- scratch (device globals; no allocation allowed) -----------
__device__ float g_X[ROWS_ * E_];        // tf32-rounded input
__device__ float g_Wq[E_ * E_];          // tf32-rounded weights
__device__ float g_Wk[E_ * E_];
__device__ float g_Wv[E_ * E_];
__device__ float g_Wo[E_ * E_];
__device__ float g_Q[BH_ * S_ * DK_];    // [bh][s][d], pre-scaled by log2e/8, tf32
__device__ float g_K[BH_ * S_ * DK_];    // tf32
__device__ float g_V[BH_ * S_ * DK_];    // tf32
__device__ float g_AO[ROWS_ * E_];       // attention output, tf32

// ---------------- helpers ----------------------------------------------------
__device__ __forceinline__ uint32_t f2tf(float x) {
    uint32_t u;
    asm("cvt.rna.tf32.f32 %0, %1;" : "=r"(u) : "f"(x));
    return u;
}
__device__ __forceinline__ uint4 cvt4(float4 v) {
    return make_uint4(f2tf(v.x), f2tf(v.y), f2tf(v.z), f2tf(v.w));
}
__device__ __forceinline__ void mma_tf32(float* d,
                                         uint32_t a0, uint32_t a1,
                                         uint32_t a2, uint32_t a3,
                                         uint32_t b0, uint32_t b1) {
    asm volatile(
        "mma.sync.aligned.m16n8k8.row.col.f32.tf32.tf32.f32 "
        "{%0,%1,%2,%3}, {%4,%5,%6,%7}, {%8,%9}, {%0,%1,%2,%3};"
        : "+f"(d[0]), "+f"(d[1]), "+f"(d[2]), "+f"(d[3])
        : "r"(a0), "r"(a1), "r"(a2), "r"(a3), "r"(b0), "r"(b1));
}
__device__ __forceinline__ void cpa16(uint32_t dst, const void* src) {
    asm volatile("cp.async.ca.shared.global [%0], [%1], 16;"
                 :: "r"(dst), "l"(src) : "memory");
}
#define CP_COMMIT() asm volatile("cp.async.commit_group;" ::: "memory")
#define CP_WAIT0()  asm volatile("cp.async.wait_group 0;" ::: "memory")

// Q prescale: 1/sqrt(64) * log2(e)  (softmax done in exp2 domain)
#define QSCALE (0.125f * 1.4426950408889634f)

// ---------------- prepass: round X + weights to tf32 in gmem ----------------
#define NX4 (ROWS_ * E_ / 4)
#define NW4 (E_ * E_ / 4)

__global__ __launch_bounds__(256)
void prepass(const float* __restrict__ X,
             const float* __restrict__ Wq, const float* __restrict__ Wk,
             const float* __restrict__ Wv, const float* __restrict__ Wo)
{
    int i = blockIdx.x * blockDim.x + threadIdx.x;
    if (i < NX4) {
        ((uint4*)g_X)[i] = cvt4(((const float4*)X)[i]);
    } else {
        int r = i - NX4;
        int wsel = r / NW4;
        r = r % NW4;
        const float4* src = (wsel == 0) ? (const float4*)Wq
                          : (wsel == 1) ? (const float4*)Wk
                          : (wsel == 2) ? (const float4*)Wv
                                        : (const float4*)Wo;
        uint4* dst = (wsel == 0) ? (uint4*)g_Wq
                   : (wsel == 1) ? (uint4*)g_Wk
                   : (wsel == 2) ? (uint4*)g_Wv
                                 : (uint4*)g_Wo;
        dst[r] = cvt4(src[r]);
    }
}

// ---------------- GEMM: C = A[8192,768] @ W[768,768] (tf32 mma) -------------
#define AP 20
#define BP 136

__global__ __launch_bounds__(256, 2)
void gemm_tc(float* __restrict__ Out, int mode)
{
    __shared__ uint32_t As[2][128 * AP];
    __shared__ uint32_t Bs[2][16 * BP];

    const float* A;
    const float* W;
    float* Dst = nullptr;
    float scale = 1.0f;
    if (mode == 1) {
        A = g_X;
        int z = blockIdx.z;
        W   = (z == 0) ? g_Wq : (z == 1) ? g_Wk : g_Wv;
        Dst = (z == 0) ? g_Q  : (z == 1) ? g_K  : g_V;
        if (z == 0) scale = QSCALE;
    } else {
        A = g_AO;
        W = g_Wo;
    }

    const int tid  = threadIdx.x;
    const int lane = tid & 31;
    const int wid  = tid >> 5;
    const int wm   = wid >> 2;
    const int wn   = wid & 3;
    const int cq   = lane >> 2;
    const int j    = lane & 3;
    const int row0 = blockIdx.y * 128;
    const int col0 = blockIdx.x * 128;

    const int ar0 = tid >> 2, ac4 = tid & 3;
    const int bk0 = tid >> 5, bc4 = tid & 31;

    const uint32_t as_base = (uint32_t)__cvta_generic_to_shared(&As[0][0]);
    const uint32_t bs_base = (uint32_t)__cvta_generic_to_shared(&Bs[0][0]);
    const uint32_t as_sz = 128 * AP * 4;
    const uint32_t bs_sz = 16 * BP * 4;

    float acc[4][4][4];
#pragma unroll
    for (int mi = 0; mi < 4; mi++)
#pragma unroll
        for (int ni = 0; ni < 4; ni++)
#pragma unroll
            for (int q = 0; q < 4; q++) acc[mi][ni][q] = 0.0f;

#pragma unroll
    for (int i = 0; i < 2; i++) {
        int r = ar0 + i * 64;
        cpa16(as_base + (r * AP + ac4 * 4) * 4,
              &A[(size_t)(row0 + r) * E_ + ac4 * 4]);
    }
#pragma unroll
    for (int i = 0; i < 2; i++) {
        int kr = bk0 + i * 8;
        cpa16(bs_base + (kr * BP + bc4 * 4) * 4,
              &W[(size_t)kr * E_ + col0 + bc4 * 4]);
    }
    CP_COMMIT();
    CP_WAIT0();
    __syncthreads();

    for (int k0 = 0; k0 < E_; k0 += 16) {
        const int p = (k0 >> 4) & 1;
        const bool pf = (k0 + 16 < E_);
        if (pf) {
#pragma unroll
            for (int i = 0; i < 2; i++) {
                int r = ar0 + i * 64;
                cpa16(as_base + (1 - p) * as_sz + (r * AP + ac4 * 4) * 4,
                      &A[(size_t)(row0 + r) * E_ + k0 + 16 + ac4 * 4]);
            }
#pragma unroll
            for (int i = 0; i < 2; i++) {
                int kr = bk0 + i * 8;
                cpa16(bs_base + (1 - p) * bs_sz + (kr * BP + bc4 * 4) * 4,
                      &W[(size_t)(k0 + 16 + kr) * E_ + col0 + bc4 * 4]);
            }
            CP_COMMIT();
        }

#pragma unroll
        for (int ks = 0; ks < 16; ks += 8) {
            uint32_t af[4][4], bf[4][2];
#pragma unroll
            for (int mi = 0; mi < 4; mi++) {
                int row = wm * 64 + mi * 16 + cq;
                int ka  = ks + j;
                af[mi][0] = As[p][row * AP + ka];
                af[mi][1] = As[p][(row + 8) * AP + ka];
                af[mi][2] = As[p][row * AP + ka + 4];
                af[mi][3] = As[p][(row + 8) * AP + ka + 4];
            }
#pragma unroll
            for (int ni = 0; ni < 4; ni++) {
                int col = wn * 32 + ni * 8 + cq;
                bf[ni][0] = Bs[p][(ks + j) * BP + col];
                bf[ni][1] = Bs[p][(ks + 4 + j) * BP + col];
            }
#pragma unroll
            for (int mi = 0; mi < 4; mi++)
#pragma unroll
                for (int ni = 0; ni < 4; ni++)
                    mma_tf32(acc[mi][ni], af[mi][0], af[mi][1], af[mi][2], af[mi][3],
                             bf[ni][0], bf[ni][1]);
        }

        if (pf) CP_WAIT0();
        __syncthreads();
    }

#pragma unroll
    for (int mi = 0; mi < 4; mi++) {
#pragma unroll
        for (int ni = 0; ni < 4; ni++) {
            int r_   = row0 + wm * 64 + mi * 16 + cq;
            int col  = col0 + wn * 32 + ni * 8 + 2 * j;
            if (mode == 1) {
                float2 v0 = make_float2(
                    __uint_as_float(f2tf(acc[mi][ni][0] * scale)),
                    __uint_as_float(f2tf(acc[mi][ni][1] * scale)));
                float2 v1 = make_float2(
                    __uint_as_float(f2tf(acc[mi][ni][2] * scale)),
                    __uint_as_float(f2tf(acc[mi][ni][3] * scale)));
                int h  = col >> 6;
                int d0 = col & 63;
                int b0b = r_ >> 12, s0s = r_ & (S_ - 1);
                *(float2*)&Dst[(((size_t)b0b * H_ + h) * S_ + s0s) * DK_ + d0] = v0;
                int r1 = r_ + 8;
                int b1b = r1 >> 12, s1s = r1 & (S_ - 1);
                *(float2*)&Dst[(((size_t)b1b * H_ + h) * S_ + s1s) * DK_ + d0] = v1;
            } else {
                *(float2*)&Out[(size_t)r_ * E_ + col] =
                    make_float2(acc[mi][ni][0], acc[mi][ni][1]);
                *(float2*)&Out[(size_t)(r_ + 8) * E_ + col] =
                    make_float2(acc[mi][ni][2], acc[mi][ni][3]);
            }
        }
    }
}

// ---------------- flash attention v4: 16 warps/SM via 2 CTAs -----------------
// CTA: 128 q-rows x 1 head, 8 warps x 16 q-rows, 2 CTAs/SM. KV tile 64, dbuf.
// PV computes O^T = V^T P^T (kv-permutation) so S C-frag == PV B-frag.
#define KP 80
#define VP 68
#define KTW (64 * KP)
#define VTW (64 * VP)
#define ATTN_SMEM ((2 * KTW + 2 * VTW) * 4)   // 75776 bytes

__global__ __launch_bounds__(256, 2)
void attn_tc_kernel()
{
    extern __shared__ uint32_t smw[];
    uint32_t* KsB[2] = { smw, smw + KTW };
    uint32_t* VsB[2] = { smw + 2 * KTW, smw + 2 * KTW + VTW };
    uint32_t ksb[2], vsb[2];
#pragma unroll
    for (int i = 0; i < 2; i++) {
        ksb[i] = (uint32_t)__cvta_generic_to_shared(KsB[i]);
        vsb[i] = (uint32_t)__cvta_generic_to_shared(VsB[i]);
    }

    const int tid  = threadIdx.x;
    const int lane = tid & 31;
    const int w    = tid >> 5;
    const int cq   = lane >> 2;
    const int j    = lane & 3;
    const int bh   = blockIdx.y;
    const int q0   = blockIdx.x * 128;

    const float* Qg  = g_Q + ((size_t)bh * S_ + q0) * DK_;
    const float* KgF = g_K + (size_t)bh * S_ * DK_;
    const float* VgF = g_V + (size_t)bh * S_ * DK_;

    // issue tile 0 -> buf 0
#pragma unroll
    for (int i = 0; i < 4; i++) {
        int idx = tid + i * 256;
        int r = idx >> 4, c4 = idx & 15;
        cpa16(ksb[0] + (r * KP + c4 * 4) * 4, KgF + idx * 4);
        cpa16(vsb[0] + (r * VP + c4 * 4) * 4, VgF + idx * 4);
    }
    CP_COMMIT();

    // Q fragments in registers (pre-rounded tf32; k-permuted slot j -> 4j+c)
    uint4 Qf[4][2];
    {
        int row = w * 16 + cq;
#pragma unroll
        for (int g = 0; g < 4; g++) {
            Qf[g][0] = *(const uint4*)&Qg[(size_t)row * DK_ + g * 16 + 4 * j];
            Qf[g][1] = *(const uint4*)&Qg[(size_t)(row + 8) * DK_ + g * 16 + 4 * j];
        }
    }

    CP_WAIT0();
    __syncthreads();

    float m_[2] = { -1e30f, -1e30f };
    float l_[2] = { 0.0f, 0.0f };

    // O^T accumulators: rows d = dt*16+cq(+8), cols q = qt*8+2j(+1)
    float o[4][2][4];
#pragma unroll
    for (int dt = 0; dt < 4; dt++)
#pragma unroll
        for (int qt = 0; qt < 2; qt++)
#pragma unroll
            for (int c = 0; c < 4; c++) o[dt][qt][c] = 0.0f;

    const int NT = S_ / 64;
    for (int kt = 0; kt < NT; kt++) {
        const int p = kt & 1;
        const uint32_t* Ks = KsB[p];
        const uint32_t* Vs = VsB[p];
        const bool pf = (kt + 1 < NT);

        if (pf) {
            const float* ksrc = KgF + (size_t)(kt + 1) * 4096;
            const float* vsrc = VgF + (size_t)(kt + 1) * 4096;
#pragma unroll
            for (int i = 0; i < 4; i++) {
                int idx = tid + i * 256;
                int r = idx >> 4, c4 = idx & 15;
                cpa16(ksb[1 - p] + (r * KP + c4 * 4) * 4, ksrc + idx * 4);
                cpa16(vsb[1 - p] + (r * VP + c4 * 4) * 4, vsrc + idx * 4);
            }
            CP_COMMIT();
        }

        // ---- S = Q K^T (scores already in log2 domain via QSCALE) ----------
        float s[8][4];
#pragma unroll
        for (int t = 0; t < 8; t++)
#pragma unroll
            for (int c = 0; c < 4; c++) s[t][c] = 0.0f;

#pragma unroll
        for (int g = 0; g < 4; g++) {
#pragma unroll
            for (int t = 0; t < 8; t++) {
                uint4 kv = *(const uint4*)&Ks[(t * 8 + cq) * KP + g * 16 + 4 * j];
                mma_tf32(s[t], Qf[g][0].x, Qf[g][1].x, Qf[g][0].y, Qf[g][1].y,
                         kv.x, kv.y);
                mma_tf32(s[t], Qf[g][0].z, Qf[g][1].z, Qf[g][0].w, Qf[g][1].w,
                         kv.z, kv.w);
            }
        }

        // ---- online softmax (exp2 domain; rows half*8 + cq) -----------------
        float aown[2];
#pragma unroll
        for (int half = 0; half < 2; half++) {
            const int c0 = half * 2;
            float mx = s[0][c0];
#pragma unroll
            for (int t = 0; t < 8; t++)
                mx = fmaxf(mx, fmaxf(s[t][c0], s[t][c0 + 1]));
            mx = fmaxf(mx, __shfl_xor_sync(0xffffffffu, mx, 1));
            mx = fmaxf(mx, __shfl_xor_sync(0xffffffffu, mx, 2));
            float mn = fmaxf(m_[half], mx);
            float al = exp2f(m_[half] - mn);
            m_[half] = mn;
            aown[half] = al;
            float rs = 0.0f;
#pragma unroll
            for (int t = 0; t < 8; t++) {
                uint32_t e0 = f2tf(exp2f(s[t][c0] - mn));
                uint32_t e1 = f2tf(exp2f(s[t][c0 + 1] - mn));
                s[t][c0]     = __uint_as_float(e0);
                s[t][c0 + 1] = __uint_as_float(e1);
                rs += __uint_as_float(e0) + __uint_as_float(e1);
            }
            rs += __shfl_xor_sync(0xffffffffu, rs, 1);
            rs += __shfl_xor_sync(0xffffffffu, rs, 2);
            l_[half] = l_[half] * al + rs;
        }

        // broadcast alphas to O^T q-columns (q-row 2j+c owned by lane (2j+c)*4+j)
        float aO[2][2];
#pragma unroll
        for (int qt = 0; qt < 2; qt++) {
            aO[qt][0] = __shfl_sync(0xffffffffu, aown[qt], ((2 * j) << 2) | j);
            aO[qt][1] = __shfl_sync(0xffffffffu, aown[qt], ((2 * j + 1) << 2) | j);
        }
#pragma unroll
        for (int dt = 0; dt < 4; dt++)
#pragma unroll
            for (int qt = 0; qt < 2; qt++) {
                o[dt][qt][0] *= aO[qt][0];
                o[dt][qt][1] *= aO[qt][1];
                o[dt][qt][2] *= aO[qt][0];
                o[dt][qt][3] *= aO[qt][1];
            }

        // ---- O^T += V^T P^T  (kv-permutation j->2j, j+4->2j+1) --------------
#pragma unroll
        for (int kb = 0; kb < 8; kb++) {
#pragma unroll
            for (int dt = 0; dt < 4; dt++) {
                const uint32_t* vrow = &Vs[(kb * 8 + 2 * j) * VP + dt * 16 + cq];
                uint32_t a0 = vrow[0];
                uint32_t a1 = vrow[8];
                uint32_t a2 = vrow[VP];
                uint32_t a3 = vrow[VP + 8];
#pragma unroll
                for (int qt = 0; qt < 2; qt++)
                    mma_tf32(o[dt][qt], a0, a1, a2, a3,
                             __float_as_uint(s[kb][qt * 2]),
                             __float_as_uint(s[kb][qt * 2 + 1]));
            }
        }

        if (pf) CP_WAIT0();
        __syncthreads();
    }

    // ---- epilogue: AO[b*s][h*64 + d], tf32-rounded --------------------------
    float lO[2][2];
#pragma unroll
    for (int qt = 0; qt < 2; qt++) {
        lO[qt][0] = 1.0f / __shfl_sync(0xffffffffu, l_[qt], ((2 * j) << 2) | j);
        lO[qt][1] = 1.0f / __shfl_sync(0xffffffffu, l_[qt], ((2 * j + 1) << 2) | j);
    }
    const int bb = bh / H_, hh = bh % H_;
#pragma unroll
    for (int qt = 0; qt < 2; qt++) {
#pragma unroll
        for (int c = 0; c < 2; c++) {
            int q = q0 + w * 16 + qt * 8 + 2 * j + c;
            float* dst = &g_AO[(size_t)(bb * S_ + q) * E_ + hh * DK_];
#pragma unroll
            for (int dt = 0; dt < 4; dt++) {
                dst[dt * 16 + cq] =
                    __uint_as_float(f2tf(o[dt][qt][c] * lO[qt][c]));
                dst[dt * 16 + cq + 8] =
                    __uint_as_float(f2tf(o[dt][qt][c + 2] * lO[qt][c]));
            }
        }
    }
}

// ---------------- launch -----------------------------------------------------
extern "C" void kernel_launch(void* const* d_in, const int* in_sizes, int n_in,
                              void* d_out, int out_size)
{
    (void)in_sizes; (void)n_in; (void)out_size;
    const float* X  = (const float*)d_in[0];
    const float* Wq = (const float*)d_in[1];
    const float* Wk = (const float*)d_in[2];
    const float* Wv = (const float*)d_in[3];
    const float* Wo = (const float*)d_in[4];
    float* out = (float*)d_out;

    cudaFuncSetAttribute(attn_tc_kernel,
                         cudaFuncAttributeMaxDynamicSharedMemorySize, ATTN_SMEM);

    // Stage 0: round X + weights to tf32 once
    prepass<<<(NX4 + 4 * NW4) / 256, 256>>>(X, Wq, Wk, Wv, Wo);
    // Stage 1: Q/K/V projections (head-major scatter, Q pre-scaled)
    gemm_tc<<<dim3(E_ / 128, ROWS_ / 128, 3), 256>>>(nullptr, 1);
    // Stage 2: tf32 mma flash attention (128 q-rows/CTA, 2 CTAs/SM)
    attn_tc_kernel<<<dim3(S_ / 128, BH_), 256, ATTN_SMEM>>>();
    // Stage 3: output projection AO @ Wo -> out
    gemm_tc<<<dim3(E_ / 128, ROWS_ / 128, 1), 256>>>(out, 0);
}

// round 7
// speedup vs baseline: 1.3050x; 1.3050x over previous
#include <cuda_runtime.h>
#include <cuda_bf16.h>
#include <cuda_fp16.h>
#include <cstdint>
#include <math.h>

// Problem constants
#define B_   2
#define S_   4096
#define E_   768
#define H_   12
#define DK_  64
#define BH_  (B_ * H_)          // 24
#define ROWS_ (B_ * S_)         // 8192

// ---------------- scratch (device globals; no allocation allowed) -----------
__device__ float  g_X[ROWS_ * E_];       // tf32-rounded input
__device__ float  g_Wq[E_ * E_];         // tf32-rounded weights
__device__ float  g_Wk[E_ * E_];
__device__ float  g_Wv[E_ * E_];
__device__ float  g_Wo[E_ * E_];
__device__ float  g_Q[BH_ * S_ * DK_];   // [bh][s][d], pre-scaled log2e/8, tf32
__device__ float  g_K[BH_ * S_ * DK_];   // tf32
__device__ __half g_Vt[BH_ * DK_ * S_];  // V TRANSPOSED: [bh][d][s], fp16
__device__ float  g_AO[ROWS_ * E_];      // attention output, tf32

// ---------------- helpers ----------------------------------------------------
__device__ __forceinline__ uint32_t f2tf(float x) {
    uint32_t u;
    asm("cvt.rna.tf32.f32 %0, %1;" : "=r"(u) : "f"(x));
    return u;
}
__device__ __forceinline__ uint4 cvt4(float4 v) {
    return make_uint4(f2tf(v.x), f2tf(v.y), f2tf(v.z), f2tf(v.w));
}
__device__ __forceinline__ void mma_tf32(float* d,
                                         uint32_t a0, uint32_t a1,
                                         uint32_t a2, uint32_t a3,
                                         uint32_t b0, uint32_t b1) {
    asm volatile(
        "mma.sync.aligned.m16n8k8.row.col.f32.tf32.tf32.f32 "
        "{%0,%1,%2,%3}, {%4,%5,%6,%7}, {%8,%9}, {%0,%1,%2,%3};"
        : "+f"(d[0]), "+f"(d[1]), "+f"(d[2]), "+f"(d[3])
        : "r"(a0), "r"(a1), "r"(a2), "r"(a3), "r"(b0), "r"(b1));
}
__device__ __forceinline__ void mma_f16(float* d,
                                        uint32_t a0, uint32_t a1,
                                        uint32_t a2, uint32_t a3,
                                        uint32_t b0, uint32_t b1) {
    asm volatile(
        "mma.sync.aligned.m16n8k16.row.col.f32.f16.f16.f32 "
        "{%0,%1,%2,%3}, {%4,%5,%6,%7}, {%8,%9}, {%0,%1,%2,%3};"
        : "+f"(d[0]), "+f"(d[1]), "+f"(d[2]), "+f"(d[3])
        : "r"(a0), "r"(a1), "r"(a2), "r"(a3), "r"(b0), "r"(b1));
}
__device__ __forceinline__ void cpa16(uint32_t dst, const void* src) {
    asm volatile("cp.async.ca.shared.global [%0], [%1], 16;"
                 :: "r"(dst), "l"(src) : "memory");
}
#define CP_COMMIT() asm volatile("cp.async.commit_group;" ::: "memory")
#define CP_WAIT0()  asm volatile("cp.async.wait_group 0;" ::: "memory")

// Q prescale: 1/sqrt(64) * log2(e)  (softmax in exp2 domain)
#define QSCALE (0.125f * 1.4426950408889634f)

// ---------------- prepass: round X + weights to tf32 in gmem ----------------
#define NX4 (ROWS_ * E_ / 4)
#define NW4 (E_ * E_ / 4)

__global__ __launch_bounds__(256)
void prepass(const float* __restrict__ X,
             const float* __restrict__ Wq, const float* __restrict__ Wk,
             const float* __restrict__ Wv, const float* __restrict__ Wo)
{
    int i = blockIdx.x * blockDim.x + threadIdx.x;
    if (i < NX4) {
        ((uint4*)g_X)[i] = cvt4(((const float4*)X)[i]);
    } else {
        int r = i - NX4;
        int wsel = r / NW4;
        r = r % NW4;
        const float4* src = (wsel == 0) ? (const float4*)Wq
                          : (wsel == 1) ? (const float4*)Wk
                          : (wsel == 2) ? (const float4*)Wv
                                        : (const float4*)Wo;
        uint4* dst = (wsel == 0) ? (uint4*)g_Wq
                   : (wsel == 1) ? (uint4*)g_Wk
                   : (wsel == 2) ? (uint4*)g_Wv
                                 : (uint4*)g_Wo;
        dst[r] = cvt4(src[r]);
    }
}

// ---------------- GEMM: C = A[8192,768] @ W[768,768] (tf32 mma) -------------
#define AP 20
#define BP 136

__global__ __launch_bounds__(256, 2)
void gemm_tc(float* __restrict__ Out, int mode)
{
    __shared__ uint32_t As[2][128 * AP];
    __shared__ uint32_t Bs[2][16 * BP];

    const float* A;
    const float* W;
    float* Dst = nullptr;
    float scale = 1.0f;
    const int z = blockIdx.z;
    if (mode == 1) {
        A = g_X;
        W   = (z == 0) ? g_Wq : (z == 1) ? g_Wk : g_Wv;
        Dst = (z == 0) ? g_Q  : (z == 1) ? g_K  : nullptr;
        if (z == 0) scale = QSCALE;
    } else {
        A = g_AO;
        W = g_Wo;
    }

    const int tid  = threadIdx.x;
    const int lane = tid & 31;
    const int wid  = tid >> 5;
    const int wm   = wid >> 2;
    const int wn   = wid & 3;
    const int cq   = lane >> 2;
    const int j    = lane & 3;
    const int row0 = blockIdx.y * 128;
    const int col0 = blockIdx.x * 128;

    const int ar0 = tid >> 2, ac4 = tid & 3;
    const int bk0 = tid >> 5, bc4 = tid & 31;

    const uint32_t as_base = (uint32_t)__cvta_generic_to_shared(&As[0][0]);
    const uint32_t bs_base = (uint32_t)__cvta_generic_to_shared(&Bs[0][0]);
    const uint32_t as_sz = 128 * AP * 4;
    const uint32_t bs_sz = 16 * BP * 4;

    float acc[4][4][4];
#pragma unroll
    for (int mi = 0; mi < 4; mi++)
#pragma unroll
        for (int ni = 0; ni < 4; ni++)
#pragma unroll
            for (int q = 0; q < 4; q++) acc[mi][ni][q] = 0.0f;

#pragma unroll
    for (int i = 0; i < 2; i++) {
        int r = ar0 + i * 64;
        cpa16(as_base + (r * AP + ac4 * 4) * 4,
              &A[(size_t)(row0 + r) * E_ + ac4 * 4]);
    }
#pragma unroll
    for (int i = 0; i < 2; i++) {
        int kr = bk0 + i * 8;
        cpa16(bs_base + (kr * BP + bc4 * 4) * 4,
              &W[(size_t)kr * E_ + col0 + bc4 * 4]);
    }
    CP_COMMIT();
    CP_WAIT0();
    __syncthreads();

    for (int k0 = 0; k0 < E_; k0 += 16) {
        const int p = (k0 >> 4) & 1;
        const bool pf = (k0 + 16 < E_);
        if (pf) {
#pragma unroll
            for (int i = 0; i < 2; i++) {
                int r = ar0 + i * 64;
                cpa16(as_base + (1 - p) * as_sz + (r * AP + ac4 * 4) * 4,
                      &A[(size_t)(row0 + r) * E_ + k0 + 16 + ac4 * 4]);
            }
#pragma unroll
            for (int i = 0; i < 2; i++) {
                int kr = bk0 + i * 8;
                cpa16(bs_base + (1 - p) * bs_sz + (kr * BP + bc4 * 4) * 4,
                      &W[(size_t)(k0 + 16 + kr) * E_ + col0 + bc4 * 4]);
            }
            CP_COMMIT();
        }

#pragma unroll
        for (int ks = 0; ks < 16; ks += 8) {
            uint32_t af[4][4], bf[4][2];
#pragma unroll
            for (int mi = 0; mi < 4; mi++) {
                int row = wm * 64 + mi * 16 + cq;
                int ka  = ks + j;
                af[mi][0] = As[p][row * AP + ka];
                af[mi][1] = As[p][(row + 8) * AP + ka];
                af[mi][2] = As[p][row * AP + ka + 4];
                af[mi][3] = As[p][(row + 8) * AP + ka + 4];
            }
#pragma unroll
            for (int ni = 0; ni < 4; ni++) {
                int col = wn * 32 + ni * 8 + cq;
                bf[ni][0] = Bs[p][(ks + j) * BP + col];
                bf[ni][1] = Bs[p][(ks + 4 + j) * BP + col];
            }
#pragma unroll
            for (int mi = 0; mi < 4; mi++)
#pragma unroll
                for (int ni = 0; ni < 4; ni++)
                    mma_tf32(acc[mi][ni], af[mi][0], af[mi][1], af[mi][2], af[mi][3],
                             bf[ni][0], bf[ni][1]);
        }

        if (pf) CP_WAIT0();
        __syncthreads();
    }

#pragma unroll
    for (int mi = 0; mi < 4; mi++) {
#pragma unroll
        for (int ni = 0; ni < 4; ni++) {
            int r_   = row0 + wm * 64 + mi * 16 + cq;
            int col  = col0 + wn * 32 + ni * 8 + 2 * j;
            if (mode == 1) {
                int h  = col >> 6;
                int d0 = col & 63;
                int b0b = r_ >> 12, s0s = r_ & (S_ - 1);
                if (z == 2) {
                    // V: store TRANSPOSED fp16 [bh][d][s]
                    __half* vb = g_Vt + ((size_t)(b0b * H_ + h) * DK_ + d0) * S_;
                    vb[s0s]          = __float2half_rn(acc[mi][ni][0]);
                    vb[S_ + s0s]     = __float2half_rn(acc[mi][ni][1]);
                    vb[s0s + 8]      = __float2half_rn(acc[mi][ni][2]);
                    vb[S_ + s0s + 8] = __float2half_rn(acc[mi][ni][3]);
                } else {
                    float2 v0 = make_float2(
                        __uint_as_float(f2tf(acc[mi][ni][0] * scale)),
                        __uint_as_float(f2tf(acc[mi][ni][1] * scale)));
                    float2 v1 = make_float2(
                        __uint_as_float(f2tf(acc[mi][ni][2] * scale)),
                        __uint_as_float(f2tf(acc[mi][ni][3] * scale)));
                    *(float2*)&Dst[(((size_t)b0b * H_ + h) * S_ + s0s) * DK_ + d0] = v0;
                    *(float2*)&Dst[(((size_t)b0b * H_ + h) * S_ + s0s + 8) * DK_ + d0] = v1;
                }
            } else {
                *(float2*)&Out[(size_t)r_ * E_ + col] =
                    make_float2(acc[mi][ni][0], acc[mi][ni][1]);
                *(float2*)&Out[(size_t)(r_ + 8) * E_ + col] =
                    make_float2(acc[mi][ni][2], acc[mi][ni][3]);
            }
        }
    }
}

// ---------------- flash attention v5: tf32 QK + fp16 PV ----------------------
// CTA: 256 q-rows x 1 head, 8 warps x 32 q-rows. KV tile 64, double-buffered.
// QK: tf32 m16n8k8, Q frags in regs. PV: fp16 m16n8k16, O^T = V^T P^T where
// the S C-fragment IS the PV B-fragment (half2-packed), V^T in fp16 smem.
#define KP  80                         // K tile row stride (words)
#define VPH 36                         // Vt row stride (words; 32 data + 4 pad)
#define KTW (64 * KP)                  // 5120 words
#define VTW (64 * VPH)                 // 2304 words
#define ATTN_SMEM ((2 * KTW + 2 * VTW) * 4)   // 59392 bytes

__global__ __launch_bounds__(256, 1)
void attn_tc_kernel()
{
    extern __shared__ uint32_t smw[];
    uint32_t* KsB[2] = { smw, smw + KTW };
    uint32_t* VsB[2] = { smw + 2 * KTW, smw + 2 * KTW + VTW };
    uint32_t ksb[2], vsb[2];
#pragma unroll
    for (int i = 0; i < 2; i++) {
        ksb[i] = (uint32_t)__cvta_generic_to_shared(KsB[i]);
        vsb[i] = (uint32_t)__cvta_generic_to_shared(VsB[i]);
    }

    const int tid  = threadIdx.x;
    const int lane = tid & 31;
    const int w    = tid >> 5;
    const int cq   = lane >> 2;
    const int j    = lane & 3;
    const int bh   = blockIdx.y;
    const int q0   = blockIdx.x * 256;

    const float*  Qg  = g_Q + ((size_t)bh * S_ + q0) * DK_;
    const float*  KgF = g_K + (size_t)bh * S_ * DK_;
    const __half* VgT = g_Vt + (size_t)bh * DK_ * S_;

    // issue tile 0 -> buf 0
#pragma unroll
    for (int i = 0; i < 4; i++) {
        int idx = tid + i * 256;
        int r = idx >> 4, c4 = idx & 15;
        cpa16(ksb[0] + (r * KP + c4 * 4) * 4, KgF + idx * 4);
    }
#pragma unroll
    for (int i = 0; i < 2; i++) {
        int idx = tid + i * 256;               // 512 chunks: d = idx>>3, c = idx&7
        int d = idx >> 3, c = idx & 7;
        cpa16(vsb[0] + (d * VPH + c * 4) * 4, VgT + (size_t)d * S_ + c * 8);
    }
    CP_COMMIT();

    // Q fragments in registers (pre-rounded tf32; k-permuted slot j -> 4j+c)
    uint4 Qf[2][4][2];
#pragma unroll
    for (int mi = 0; mi < 2; mi++) {
        int row = w * 32 + mi * 16 + cq;
#pragma unroll
        for (int g = 0; g < 4; g++) {
            Qf[mi][g][0] = *(const uint4*)&Qg[(size_t)row * DK_ + g * 16 + 4 * j];
            Qf[mi][g][1] = *(const uint4*)&Qg[(size_t)(row + 8) * DK_ + g * 16 + 4 * j];
        }
    }

    CP_WAIT0();
    __syncthreads();

    float m_[2][2], l_[2][2];
#pragma unroll
    for (int a = 0; a < 2; a++)
#pragma unroll
        for (int b = 0; b < 2; b++) { m_[a][b] = -1e30f; l_[a][b] = 0.0f; }

    // O^T accumulators: rows d = dt*16+cq(+8), cols q = (qt-group)*8 + 2j(+1)
    float o[4][4][4];
#pragma unroll
    for (int dt = 0; dt < 4; dt++)
#pragma unroll
        for (int qt = 0; qt < 4; qt++)
#pragma unroll
            for (int c = 0; c < 4; c++) o[dt][qt][c] = 0.0f;

    const int NT = S_ / 64;
    for (int kt = 0; kt < NT; kt++) {
        const int p = kt & 1;
        const uint32_t* Ks = KsB[p];
        const uint32_t* Vs = VsB[p];
        const bool pf = (kt + 1 < NT);

        if (pf) {
            const float*  ksrc = KgF + (size_t)(kt + 1) * 4096;
            const __half* vsrc = VgT + (kt + 1) * 64;
#pragma unroll
            for (int i = 0; i < 4; i++) {
                int idx = tid + i * 256;
                int r = idx >> 4, c4 = idx & 15;
                cpa16(ksb[1 - p] + (r * KP + c4 * 4) * 4, ksrc + idx * 4);
            }
#pragma unroll
            for (int i = 0; i < 2; i++) {
                int idx = tid + i * 256;
                int d = idx >> 3, c = idx & 7;
                cpa16(vsb[1 - p] + (d * VPH + c * 4) * 4,
                      vsrc + (size_t)d * S_ + c * 8);
            }
            CP_COMMIT();
        }

        // ---- S = Q K^T (tf32; scores in log2 domain via QSCALE) ------------
        float s[2][8][4];
#pragma unroll
        for (int mi = 0; mi < 2; mi++)
#pragma unroll
            for (int t = 0; t < 8; t++)
#pragma unroll
                for (int c = 0; c < 4; c++) s[mi][t][c] = 0.0f;

#pragma unroll
        for (int g = 0; g < 4; g++) {
#pragma unroll
            for (int t = 0; t < 8; t++) {
                uint4 kv = *(const uint4*)&Ks[(t * 8 + cq) * KP + g * 16 + 4 * j];
#pragma unroll
                for (int mi = 0; mi < 2; mi++) {
                    mma_tf32(s[mi][t], Qf[mi][g][0].x, Qf[mi][g][1].x,
                             Qf[mi][g][0].y, Qf[mi][g][1].y, kv.x, kv.y);
                    mma_tf32(s[mi][t], Qf[mi][g][0].z, Qf[mi][g][1].z,
                             Qf[mi][g][0].w, Qf[mi][g][1].w, kv.z, kv.w);
                }
            }
        }

        // ---- online softmax (exp2 domain); P packed to half2 ----------------
        uint32_t s2[2][8][2];            // [mi][t][hf]: half2(p@q=cq.. , next kv)
        float aown[2][2];
#pragma unroll
        for (int mi = 0; mi < 2; mi++) {
#pragma unroll
            for (int hf = 0; hf < 2; hf++) {
                const int c0 = hf * 2;
                float mx = s[mi][0][c0];
#pragma unroll
                for (int t = 0; t < 8; t++)
                    mx = fmaxf(mx, fmaxf(s[mi][t][c0], s[mi][t][c0 + 1]));
                mx = fmaxf(mx, __shfl_xor_sync(0xffffffffu, mx, 1));
                mx = fmaxf(mx, __shfl_xor_sync(0xffffffffu, mx, 2));
                float mn = fmaxf(m_[mi][hf], mx);
                float al = exp2f(m_[mi][hf] - mn);
                m_[mi][hf] = mn;
                aown[mi][hf] = al;
                float rs = 0.0f;
#pragma unroll
                for (int t = 0; t < 8; t++) {
                    float e0 = exp2f(s[mi][t][c0] - mn);
                    float e1 = exp2f(s[mi][t][c0 + 1] - mn);
                    __half2 hp = __floats2half2_rn(e0, e1);
                    s2[mi][t][hf] = *(uint32_t*)&hp;
                    float2 pf2 = __half22float2(hp);   // sum the ROUNDED p's
                    rs += pf2.x + pf2.y;
                }
                rs += __shfl_xor_sync(0xffffffffu, rs, 1);
                rs += __shfl_xor_sync(0xffffffffu, rs, 2);
                l_[mi][hf] = l_[mi][hf] * al + rs;
            }
        }

        // broadcast alphas to O^T q-columns (q-col 2j+c owned by lane (2j+c)*4+j)
        float aO[4][2];
#pragma unroll
        for (int qt = 0; qt < 4; qt++) {
            float av = aown[qt >> 1][qt & 1];
            aO[qt][0] = __shfl_sync(0xffffffffu, av, ((2 * j) << 2) | j);
            aO[qt][1] = __shfl_sync(0xffffffffu, av, ((2 * j + 1) << 2) | j);
        }
#pragma unroll
        for (int dt = 0; dt < 4; dt++)
#pragma unroll
            for (int qt = 0; qt < 4; qt++) {
                o[dt][qt][0] *= aO[qt][0];
                o[dt][qt][1] *= aO[qt][1];
                o[dt][qt][2] *= aO[qt][0];
                o[dt][qt][3] *= aO[qt][1];
            }

        // ---- O^T += V^T P^T  (fp16 m16n8k16; S C-frag == PV B-frag) ---------
#pragma unroll
        for (int kb = 0; kb < 4; kb++) {
#pragma unroll
            for (int dt = 0; dt < 4; dt++) {
                const uint32_t* vr0 = &Vs[(dt * 16 + cq) * VPH + kb * 8 + j];
                const uint32_t* vr1 = &Vs[(dt * 16 + cq + 8) * VPH + kb * 8 + j];
                uint32_t a0 = vr0[0];
                uint32_t a1 = vr1[0];
                uint32_t a2 = vr0[4];
                uint32_t a3 = vr1[4];
#pragma unroll
                for (int qt = 0; qt < 4; qt++) {
                    const int mi = qt >> 1, hf = qt & 1;
                    mma_f16(o[dt][qt], a0, a1, a2, a3,
                            s2[mi][2 * kb][hf], s2[mi][2 * kb + 1][hf]);
                }
            }
        }

        if (pf) CP_WAIT0();
        __syncthreads();
    }

    // ---- epilogue: AO[b*s][h*64 + d], tf32-rounded --------------------------
    float lO[4][2];
#pragma unroll
    for (int qt = 0; qt < 4; qt++) {
        float lv = l_[qt >> 1][qt & 1];
        lO[qt][0] = 1.0f / __shfl_sync(0xffffffffu, lv, ((2 * j) << 2) | j);
        lO[qt][1] = 1.0f / __shfl_sync(0xffffffffu, lv, ((2 * j + 1) << 2) | j);
    }
    const int bb = bh / H_, hh = bh % H_;
#pragma unroll
    for (int qt = 0; qt < 4; qt++) {
#pragma unroll
        for (int c = 0; c < 2; c++) {
            int q = q0 + w * 32 + (qt >> 1) * 16 + (qt & 1) * 8 + 2 * j + c;
            float* dst = &g_AO[(size_t)(bb * S_ + q) * E_ + hh * DK_];
#pragma unroll
            for (int dt = 0; dt < 4; dt++) {
                dst[dt * 16 + cq] =
                    __uint_as_float(f2tf(o[dt][qt][c] * lO[qt][c]));
                dst[dt * 16 + cq + 8] =
                    __uint_as_float(f2tf(o[dt][qt][c + 2] * lO[qt][c]));
            }
        }
    }
}

// ---------------- launch -----------------------------------------------------
extern "C" void kernel_launch(void* const* d_in, const int* in_sizes, int n_in,
                              void* d_out, int out_size)
{
    (void)in_sizes; (void)n_in; (void)out_size;
    const float* X  = (const float*)d_in[0];
    const float* Wq = (const float*)d_in[1];
    const float* Wk = (const float*)d_in[2];
    const float* Wv = (const float*)d_in[3];
    const float* Wo = (const float*)d_in[4];
    float* out = (float*)d_out;

    cudaFuncSetAttribute(attn_tc_kernel,
                         cudaFuncAttributeMaxDynamicSharedMemorySize, ATTN_SMEM);

    // Stage 0: round X + weights to tf32 once
    prepass<<<(NX4 + 4 * NW4) / 256, 256>>>(X, Wq, Wk, Wv, Wo);
    // Stage 1: Q/K/V projections (Q,K head-major tf32; V transposed fp16)
    gemm_tc<<<dim3(E_ / 128, ROWS_ / 128, 3), 256>>>(nullptr, 1);
    // Stage 2: flash attention (tf32 QK + fp16 PV)
    attn_tc_kernel<<<dim3(S_ / 256, BH_), 256, ATTN_SMEM>>>();
    // Stage 3: output projection AO @ Wo -> out
    gemm_tc<<<dim3(E_ / 128, ROWS_ / 128, 1), 256>>>(out, 0);
}

// round 8
// speedup vs baseline: 1.9960x; 1.5296x over previous
#include <cuda_runtime.h>
#include <cuda_bf16.h>
#include <cuda_fp16.h>
#include <cstdint>
#include <math.h>

// Problem constants
#define B_   2
#define S_   4096
#define E_   768
#define H_   12
#define DK_  64
#define BH_  (B_ * H_)          // 24
#define ROWS_ (B_ * S_)         // 8192

// ---------------- scratch (device globals; no allocation allowed) -----------
__device__ __half g_Xh[ROWS_ * E_];       // fp16 input
__device__ __half g_Wt[4][E_ * E_];       // W^T [n][k] fp16: q,k,v,o
__device__ __half g_Qh[BH_ * S_ * DK_];   // [bh][s][d], pre-scaled log2e/8
__device__ __half g_Kh[BH_ * S_ * DK_];
__device__ __half g_Vt[BH_ * DK_ * S_];   // V transposed [bh][d][s]
__device__ __half g_AOh[ROWS_ * E_];      // attention output fp16

// ---------------- helpers ----------------------------------------------------
__device__ __forceinline__ void mma_f16(float* d,
                                        uint32_t a0, uint32_t a1,
                                        uint32_t a2, uint32_t a3,
                                        uint32_t b0, uint32_t b1) {
    asm volatile(
        "mma.sync.aligned.m16n8k16.row.col.f32.f16.f16.f32 "
        "{%0,%1,%2,%3}, {%4,%5,%6,%7}, {%8,%9}, {%0,%1,%2,%3};"
        : "+f"(d[0]), "+f"(d[1]), "+f"(d[2]), "+f"(d[3])
        : "r"(a0), "r"(a1), "r"(a2), "r"(a3), "r"(b0), "r"(b1));
}
__device__ __forceinline__ void ldsm4(uint32_t& r0, uint32_t& r1,
                                      uint32_t& r2, uint32_t& r3, uint32_t a) {
    asm volatile("ldmatrix.sync.aligned.m8n8.x4.shared.b16 {%0,%1,%2,%3}, [%4];"
                 : "=r"(r0), "=r"(r1), "=r"(r2), "=r"(r3) : "r"(a));
}
__device__ __forceinline__ void cpa16(uint32_t dst, const void* src) {
    asm volatile("cp.async.ca.shared.global [%0], [%1], 16;"
                 :: "r"(dst), "l"(src) : "memory");
}
#define CP_COMMIT() asm volatile("cp.async.commit_group;" ::: "memory")
#define CP_WAIT0()  asm volatile("cp.async.wait_group 0;" ::: "memory")

// Q prescale: 1/sqrt(64) * log2(e)  (softmax in exp2 domain)
#define QSCALE (0.125f * 1.4426950408889634f)

// ---------------- prepass ----------------------------------------------------
__global__ __launch_bounds__(256)
void prep_x(const float* __restrict__ X)
{
    int i = blockIdx.x * 256 + threadIdx.x;    // ROWS_*E_/4 elements
    float4 v = ((const float4*)X)[i];
    __half2 h0 = __floats2half2_rn(v.x, v.y);
    __half2 h1 = __floats2half2_rn(v.z, v.w);
    uint2 u = make_uint2(*(uint32_t*)&h0, *(uint32_t*)&h1);
    ((uint2*)g_Xh)[i] = u;
}

// transpose + fp16: Wt[z][n][k] = W[k][n]
__global__ __launch_bounds__(256)
void prep_wt(const float* __restrict__ Wq, const float* __restrict__ Wk,
             const float* __restrict__ Wv, const float* __restrict__ Wo)
{
    __shared__ float t[32][33];
    const float* W = (blockIdx.z == 0) ? Wq : (blockIdx.z == 1) ? Wk
                   : (blockIdx.z == 2) ? Wv : Wo;
    __half* Wt = g_Wt[blockIdx.z];
    int k0 = blockIdx.x * 32, n0 = blockIdx.y * 32;
    int tx = threadIdx.x & 31, ty = threadIdx.x >> 5;   // 32 x 8
#pragma unroll
    for (int i = 0; i < 4; i++)
        t[ty + 8 * i][tx] = W[(size_t)(k0 + ty + 8 * i) * E_ + n0 + tx];
    __syncthreads();
#pragma unroll
    for (int i = 0; i < 4; i++)
        Wt[(size_t)(n0 + ty + 8 * i) * E_ + k0 + tx] =
            __float2half_rn(t[tx][ty + 8 * i]);
}

// ---------------- GEMM fp16: C = A[8192,768] @ W[768,768] -------------------
// BM=128, BN=128, BK=32. A fp16 row-major, W^T fp16 [n][k]. ldmatrix frags.
#define SWG 20    // smem row stride (words): 16 data + 4 pad; 20r%32 distinct

__global__ __launch_bounds__(256, 2)
void gemm_h(float* __restrict__ Out, int mode)
{
    __shared__ __align__(16) uint32_t As[2][128 * SWG];
    __shared__ __align__(16) uint32_t Bs[2][128 * SWG];

    const __half* A;
    const __half* Wt;
    const int z = blockIdx.z;
    float scale = 1.0f;
    if (mode == 1) {
        A  = g_Xh;
        Wt = g_Wt[z];
        if (z == 0) scale = QSCALE;
    } else {
        A  = g_AOh;
        Wt = g_Wt[3];
    }

    const int tid  = threadIdx.x;
    const int lane = tid & 31;
    const int wid  = tid >> 5;
    const int wm   = wid >> 2;
    const int wn   = wid & 3;
    const int cq   = lane >> 2;
    const int j    = lane & 3;
    const int row0 = blockIdx.y * 128;
    const int col0 = blockIdx.x * 128;

    // ldmatrix per-lane coords
    const int lg = lane >> 3, lr = lane & 7;
    const int frow = (lg & 1) * 8 + lr;
    const int fkw  = (lg >> 1) * 4;

    // cp.async coords: 512 chunks/tile, 2 per thread
    const int cr  = tid >> 1;            // 0..127 row
    const int cc4 = (tid & 1) * 2;       // chunk col 0 or 2 (+1 inner)

    const uint32_t as_base = (uint32_t)__cvta_generic_to_shared(&As[0][0]);
    const uint32_t bs_base = (uint32_t)__cvta_generic_to_shared(&Bs[0][0]);
    const uint32_t buf_sz = 128 * SWG * 4;

    float acc[4][4][4];
#pragma unroll
    for (int mi = 0; mi < 4; mi++)
#pragma unroll
        for (int ni = 0; ni < 4; ni++)
#pragma unroll
            for (int q = 0; q < 4; q++) acc[mi][ni][q] = 0.0f;

    // prologue: stage 0
#pragma unroll
    for (int c = 0; c < 2; c++) {
        cpa16(as_base + (cr * SWG + (cc4 + c) * 4) * 4,
              A + (size_t)(row0 + cr) * E_ + (cc4 + c) * 8);
        cpa16(bs_base + (cr * SWG + (cc4 + c) * 4) * 4,
              Wt + (size_t)(col0 + cr) * E_ + (cc4 + c) * 8);
    }
    CP_COMMIT();
    CP_WAIT0();
    __syncthreads();

    for (int k0 = 0; k0 < E_; k0 += 32) {
        const int p = (k0 >> 5) & 1;
        const bool pf = (k0 + 32 < E_);
        if (pf) {
#pragma unroll
            for (int c = 0; c < 2; c++) {
                cpa16(as_base + (1 - p) * buf_sz + (cr * SWG + (cc4 + c) * 4) * 4,
                      A + (size_t)(row0 + cr) * E_ + k0 + 32 + (cc4 + c) * 8);
                cpa16(bs_base + (1 - p) * buf_sz + (cr * SWG + (cc4 + c) * 4) * 4,
                      Wt + (size_t)(col0 + cr) * E_ + k0 + 32 + (cc4 + c) * 8);
            }
            CP_COMMIT();
        }

#pragma unroll
        for (int ks = 0; ks < 2; ks++) {
            uint32_t af[4][4], bf[2][4];
#pragma unroll
            for (int mi = 0; mi < 4; mi++)
                ldsm4(af[mi][0], af[mi][1], af[mi][2], af[mi][3],
                      as_base + p * buf_sz +
                      ((wm * 64 + mi * 16 + frow) * SWG + ks * 8 + fkw) * 4);
#pragma unroll
            for (int pr = 0; pr < 2; pr++)
                ldsm4(bf[pr][0], bf[pr][1], bf[pr][2], bf[pr][3],
                      bs_base + p * buf_sz +
                      ((wn * 32 + pr * 16 + frow) * SWG + ks * 8 + fkw) * 4);
#pragma unroll
            for (int mi = 0; mi < 4; mi++)
#pragma unroll
                for (int ni = 0; ni < 4; ni++)
                    mma_f16(acc[mi][ni], af[mi][0], af[mi][1], af[mi][2], af[mi][3],
                            bf[ni >> 1][ni & 1], bf[ni >> 1][(ni & 1) + 2]);
        }

        if (pf) CP_WAIT0();
        __syncthreads();
    }

    // epilogue (frag: c0,c1 = row r_, cols col,col+1; c2,c3 = row r_+8)
#pragma unroll
    for (int mi = 0; mi < 4; mi++) {
#pragma unroll
        for (int ni = 0; ni < 4; ni++) {
            int r_  = row0 + wm * 64 + mi * 16 + cq;
            int col = col0 + wn * 32 + ni * 8 + 2 * j;
            if (mode == 1) {
                int h  = col >> 6;
                int d0 = col & 63;
                int bb = r_ >> 12, ss = r_ & (S_ - 1);
                if (z == 2) {
                    __half* vb = g_Vt + ((size_t)(bb * H_ + h) * DK_ + d0) * S_;
                    vb[ss]          = __float2half_rn(acc[mi][ni][0]);
                    vb[S_ + ss]     = __float2half_rn(acc[mi][ni][1]);
                    vb[ss + 8]      = __float2half_rn(acc[mi][ni][2]);
                    vb[S_ + ss + 8] = __float2half_rn(acc[mi][ni][3]);
                } else {
                    __half* Dst = (z == 0) ? g_Qh : g_Kh;
                    __half2 v0 = __floats2half2_rn(acc[mi][ni][0] * scale,
                                                   acc[mi][ni][1] * scale);
                    __half2 v1 = __floats2half2_rn(acc[mi][ni][2] * scale,
                                                   acc[mi][ni][3] * scale);
                    *(__half2*)&Dst[(((size_t)bb * H_ + h) * S_ + ss) * DK_ + d0] = v0;
                    *(__half2*)&Dst[(((size_t)bb * H_ + h) * S_ + ss + 8) * DK_ + d0] = v1;
                }
            } else {
                *(float2*)&Out[(size_t)r_ * E_ + col] =
                    make_float2(acc[mi][ni][0], acc[mi][ni][1]);
                *(float2*)&Out[(size_t)(r_ + 8) * E_ + col] =
                    make_float2(acc[mi][ni][2], acc[mi][ni][3]);
            }
        }
    }
}

// ---------------- flash attention: all-fp16 mma + ldmatrix -------------------
// CTA: 256 q-rows x 1 head, 8 warps x 32 q-rows (2 m-tiles). KV tile 64, dbuf.
// QK: fp16 k16, Q frags in regs, K frags via ldmatrix. PV: fp16 k16, V^T via
// ldmatrix; the S C-fragment IS the PV B-fragment (half2-packed).
#define SWA 36    // smem row stride (words): 32 data + 4 pad; 4r%32 distinct
#define ATILE (64 * SWA)                  // words per tile buffer

__global__ __launch_bounds__(256, 1)
void attn_h()
{
    __shared__ __align__(16) uint32_t KsB[2][ATILE];
    __shared__ __align__(16) uint32_t VsB[2][ATILE];
    const uint32_t ks0 = (uint32_t)__cvta_generic_to_shared(&KsB[0][0]);
    const uint32_t vs0 = (uint32_t)__cvta_generic_to_shared(&VsB[0][0]);
    const uint32_t tsz = ATILE * 4;

    const int tid  = threadIdx.x;
    const int lane = tid & 31;
    const int w    = tid >> 5;
    const int cq   = lane >> 2;
    const int j    = lane & 3;
    const int bh   = blockIdx.y;
    const int q0   = blockIdx.x * 256;

    const int lg = lane >> 3, lr = lane & 7;
    const int frow = (lg & 1) * 8 + lr;
    const int fkw  = (lg >> 1) * 4;

    const __half* Qg  = g_Qh + ((size_t)bh * S_ + q0) * DK_;
    const __half* Kg  = g_Kh + (size_t)bh * S_ * DK_;
    const __half* VgT = g_Vt + (size_t)bh * DK_ * S_;

    // cp.async coords: 512 chunks per 64x64-half tile, 2 per thread
    const int cr  = tid >> 2;            // 0..63 row
    const int cc  = (tid & 3) * 2;       // chunk 0..7 (two: cc, cc+1)

    // tile 0 -> buf 0
#pragma unroll
    for (int c = 0; c < 2; c++) {
        cpa16(ks0 + (cr * SWA + (cc + c) * 4) * 4, Kg + cr * 64 + (cc + c) * 8);
        cpa16(vs0 + (cr * SWA + (cc + c) * 4) * 4,
              VgT + (size_t)cr * S_ + (cc + c) * 8);
    }
    CP_COMMIT();

    // Q fragments in regs: Qf[mi][kg] = a0..a3 (one-time LDG)
    uint32_t Qf[2][4][4];
#pragma unroll
    for (int mi = 0; mi < 2; mi++) {
        int row = w * 32 + mi * 16 + cq;
#pragma unroll
        for (int kg = 0; kg < 4; kg++) {
            Qf[mi][kg][0] = *(const uint32_t*)&Qg[(size_t)row * DK_ + kg * 16 + 2 * j];
            Qf[mi][kg][1] = *(const uint32_t*)&Qg[(size_t)(row + 8) * DK_ + kg * 16 + 2 * j];
            Qf[mi][kg][2] = *(const uint32_t*)&Qg[(size_t)row * DK_ + kg * 16 + 8 + 2 * j];
            Qf[mi][kg][3] = *(const uint32_t*)&Qg[(size_t)(row + 8) * DK_ + kg * 16 + 8 + 2 * j];
        }
    }

    CP_WAIT0();
    __syncthreads();

    float m_[2][2], l_[2][2];
#pragma unroll
    for (int a = 0; a < 2; a++)
#pragma unroll
        for (int b = 0; b < 2; b++) { m_[a][b] = -1e30f; l_[a][b] = 0.0f; }

    // O^T accumulators: rows d = dt*16+cq(+8), cols q-sub = 2j(+1)
    float o[4][4][4];
#pragma unroll
    for (int dt = 0; dt < 4; dt++)
#pragma unroll
        for (int qt = 0; qt < 4; qt++)
#pragma unroll
            for (int c = 0; c < 4; c++) o[dt][qt][c] = 0.0f;

    const int NT = S_ / 64;
    for (int kt = 0; kt < NT; kt++) {
        const int p = kt & 1;
        const uint32_t ksb = ks0 + p * tsz;
        const uint32_t vsb = vs0 + p * tsz;
        const bool pf = (kt + 1 < NT);

        if (pf) {
            const __half* ksrc = Kg + (size_t)(kt + 1) * 64 * 64;
            const __half* vsrc = VgT + (kt + 1) * 64;
#pragma unroll
            for (int c = 0; c < 2; c++) {
                cpa16(ks0 + (1 - p) * tsz + (cr * SWA + (cc + c) * 4) * 4,
                      ksrc + cr * 64 + (cc + c) * 8);
                cpa16(vs0 + (1 - p) * tsz + (cr * SWA + (cc + c) * 4) * 4,
                      vsrc + (size_t)cr * S_ + (cc + c) * 8);
            }
            CP_COMMIT();
        }

        // ---- S = Q K^T (fp16 k16; scores in log2 domain) --------------------
        float s[2][8][4];
#pragma unroll
        for (int mi = 0; mi < 2; mi++)
#pragma unroll
            for (int t = 0; t < 8; t++)
#pragma unroll
                for (int c = 0; c < 4; c++) s[mi][t][c] = 0.0f;

#pragma unroll
        for (int kg = 0; kg < 4; kg++) {
#pragma unroll
            for (int tp = 0; tp < 4; tp++) {   // kv-tile pairs (16 kv each)
                uint32_t kr0, kr1, kr2, kr3;
                ldsm4(kr0, kr1, kr2, kr3,
                      ksb + ((tp * 16 + frow) * SWA + kg * 8 + fkw) * 4);
#pragma unroll
                for (int mi = 0; mi < 2; mi++) {
                    mma_f16(s[mi][2 * tp],     Qf[mi][kg][0], Qf[mi][kg][1],
                            Qf[mi][kg][2], Qf[mi][kg][3], kr0, kr2);
                    mma_f16(s[mi][2 * tp + 1], Qf[mi][kg][0], Qf[mi][kg][1],
                            Qf[mi][kg][2], Qf[mi][kg][3], kr1, kr3);
                }
            }
        }

        // ---- online softmax (exp2 domain); P packed to half2 ----------------
        uint32_t s2[2][8][2];
        float aown[2][2];
#pragma unroll
        for (int mi = 0; mi < 2; mi++) {
#pragma unroll
            for (int hf = 0; hf < 2; hf++) {
                const int c0 = hf * 2;
                float mx = s[mi][0][c0];
#pragma unroll
                for (int t = 0; t < 8; t++)
                    mx = fmaxf(mx, fmaxf(s[mi][t][c0], s[mi][t][c0 + 1]));
                mx = fmaxf(mx, __shfl_xor_sync(0xffffffffu, mx, 1));
                mx = fmaxf(mx, __shfl_xor_sync(0xffffffffu, mx, 2));
                float mn = fmaxf(m_[mi][hf], mx);
                float al = exp2f(m_[mi][hf] - mn);
                m_[mi][hf] = mn;
                aown[mi][hf] = al;
                float rs = 0.0f;
#pragma unroll
                for (int t = 0; t < 8; t++) {
                    float e0 = exp2f(s[mi][t][c0] - mn);
                    float e1 = exp2f(s[mi][t][c0 + 1] - mn);
                    __half2 hp = __floats2half2_rn(e0, e1);
                    s2[mi][t][hf] = *(uint32_t*)&hp;
                    float2 pf2 = __half22float2(hp);   // sum the ROUNDED p's
                    rs += pf2.x + pf2.y;
                }
                rs += __shfl_xor_sync(0xffffffffu, rs, 1);
                rs += __shfl_xor_sync(0xffffffffu, rs, 2);
                l_[mi][hf] = l_[mi][hf] * al + rs;
            }
        }

        // broadcast alphas to O^T q-columns (q-col 2j+c owned by lane (2j+c)*4+j)
        float aO[4][2];
#pragma unroll
        for (int qt = 0; qt < 4; qt++) {
            float av = aown[qt >> 1][qt & 1];
            aO[qt][0] = __shfl_sync(0xffffffffu, av, ((2 * j) << 2) | j);
            aO[qt][1] = __shfl_sync(0xffffffffu, av, ((2 * j + 1) << 2) | j);
        }
#pragma unroll
        for (int dt = 0; dt < 4; dt++)
#pragma unroll
            for (int qt = 0; qt < 4; qt++) {
                o[dt][qt][0] *= aO[qt][0];
                o[dt][qt][1] *= aO[qt][1];
                o[dt][qt][2] *= aO[qt][0];
                o[dt][qt][3] *= aO[qt][1];
            }

        // ---- O^T += V^T P^T  (S C-frag == PV B-frag) ------------------------
#pragma unroll
        for (int kb = 0; kb < 4; kb++) {
#pragma unroll
            for (int dt = 0; dt < 4; dt++) {
                uint32_t va0, va1, va2, va3;
                ldsm4(va0, va1, va2, va3,
                      vsb + ((dt * 16 + frow) * SWA + kb * 8 + fkw) * 4);
#pragma unroll
                for (int qt = 0; qt < 4; qt++) {
                    const int mi = qt >> 1, hf = qt & 1;
                    mma_f16(o[dt][qt], va0, va1, va2, va3,
                            s2[mi][2 * kb][hf], s2[mi][2 * kb + 1][hf]);
                }
            }
        }

        if (pf) CP_WAIT0();
        __syncthreads();
    }

    // ---- epilogue: AO fp16 [b*s][h*64 + d] ----------------------------------
    float lO[4][2];
#pragma unroll
    for (int qt = 0; qt < 4; qt++) {
        float lv = l_[qt >> 1][qt & 1];
        lO[qt][0] = 1.0f / __shfl_sync(0xffffffffu, lv, ((2 * j) << 2) | j);
        lO[qt][1] = 1.0f / __shfl_sync(0xffffffffu, lv, ((2 * j + 1) << 2) | j);
    }
    const int bb = bh / H_, hh = bh % H_;
#pragma unroll
    for (int qt = 0; qt < 4; qt++) {
#pragma unroll
        for (int c = 0; c < 2; c++) {
            int q = q0 + w * 32 + (qt >> 1) * 16 + (qt & 1) * 8 + 2 * j + c;
            __half* dst = &g_AOh[(size_t)(bb * S_ + q) * E_ + hh * DK_];
#pragma unroll
            for (int dt = 0; dt < 4; dt++) {
                dst[dt * 16 + cq]     = __float2half_rn(o[dt][qt][c] * lO[qt][c]);
                dst[dt * 16 + cq + 8] = __float2half_rn(o[dt][qt][c + 2] * lO[qt][c]);
            }
        }
    }
}

// ---------------- launch -----------------------------------------------------
extern "C" void kernel_launch(void* const* d_in, const int* in_sizes, int n_in,
                              void* d_out, int out_size)
{
    (void)in_sizes; (void)n_in; (void)out_size;
    const float* X  = (const float*)d_in[0];
    const float* Wq = (const float*)d_in[1];
    const float* Wk = (const float*)d_in[2];
    const float* Wv = (const float*)d_in[3];
    const float* Wo = (const float*)d_in[4];
    float* out = (float*)d_out;

    // Stage 0: fp16 conversions (X) + weight transposes (W^T)
    prep_x<<<ROWS_ * E_ / 4 / 256, 256>>>(X);
    prep_wt<<<dim3(E_ / 32, E_ / 32, 4), 256>>>(Wq, Wk, Wv, Wo);
    // Stage 1: Q/K/V projections (Q,K head-major fp16; V transposed fp16)
    gemm_h<<<dim3(E_ / 128, ROWS_ / 128, 3), 256>>>(nullptr, 1);
    // Stage 2: all-fp16 flash attention
    attn_h<<<dim3(S_ / 256, BH_), 256>>>();
    // Stage 3: output projection AO @ Wo -> out (fp32)
    gemm_h<<<dim3(E_ / 128, ROWS_ / 128, 1), 256>>>(out, 0);
}